// round 2
// baseline (speedup 1.0000x reference)
#include <cuda_runtime.h>
#include <math.h>

#define Nn 50000
#define Ee 300000
#define Mm (Ee + Nn)
#define IND 64
#define Hh 256
#define Ll 4
#define NBc 181
#define Gg 64

// ---------------- scratch (device globals; no allocation allowed) ----------------
__device__ float g_x[Nn * Hh];
__device__ float g_xl[Nn * Hh];
__device__ float g_xr[Nn * Hh];
__device__ float g_out[Nn * Hh];
__device__ float g_e[Mm];
__device__ float g_nmax[Nn];
__device__ float g_nsum[Nn];
__device__ float g_gate[Nn];
__device__ float g_bmax[Gg];
__device__ float g_bsum[Gg];
__device__ float g_pooled[Gg * Hh];
__device__ int   g_idx64;

// ---------------- helpers ----------------
__device__ __forceinline__ void atomicMaxF(float* addr, float val) {
    // float-max via monotone int/uint encoding (no NaNs in this workload)
    if (val >= 0.f) atomicMax((int*)addr, __float_as_int(val));
    else            atomicMin((unsigned int*)addr, __float_as_uint(val));
}

__device__ __forceinline__ int load_idx(const void* p, long long i, int is64) {
    return is64 ? (int)((const long long*)p)[i] : ((const int*)p)[i];
}

// Detect whether index tensors are int64 or int32. If the buffer really holds
// int32 pairs, interpreting as int64 yields values >= Nn with overwhelming
// probability within 64 samples (values are uniform in [0, 50000)).
__global__ void detect_kernel(const void* ei) {
    const long long* p = (const long long*)ei;
    int ok = 1;
    for (int i = 0; i < 64; i++) {
        long long v = p[i];
        if (v < 0 || v >= Nn) { ok = 0; break; }
    }
    g_idx64 = ok;
}

__global__ void fill_kernel(float* p, float v, int n) {
    int i = blockIdx.x * blockDim.x + threadIdx.x;
    if (i < n) p[i] = v;
}

// ---------------- SGEMM:  C[n, 256] = A[n,K] @ W[256,K]^T + bias  ----------------
// 64x64 block tile, 256 threads, 4x4 register micro-tile, K-tile 16.
__global__ void sgemm_tn_kernel(const float* __restrict__ A, const float* __restrict__ W,
                                const float* __restrict__ bias, float* __restrict__ C,
                                int n, int K, int relu) {
    __shared__ float As[16][68];
    __shared__ float Bs[16][68];
    const int tx = threadIdx.x;
    const int row0 = blockIdx.y * 64;
    const int col0 = blockIdx.x * 64;
    const int tr = (tx >> 4) << 2;
    const int tc = (tx & 15) << 2;
    float acc[4][4];
#pragma unroll
    for (int i = 0; i < 4; i++)
#pragma unroll
        for (int j = 0; j < 4; j++) acc[i][j] = 0.f;

    for (int kt = 0; kt < K; kt += 16) {
#pragma unroll
        for (int i = 0; i < 4; i++) {
            int idx = tx + i * 256;
            int r = idx >> 4, kk = idx & 15;
            int gr = row0 + r;
            As[kk][r] = (gr < n) ? A[(size_t)gr * K + kt + kk] : 0.f;
            Bs[kk][r] = W[(size_t)(col0 + r) * K + kt + kk];
        }
        __syncthreads();
#pragma unroll
        for (int kk = 0; kk < 16; kk++) {
            float a[4], b[4];
#pragma unroll
            for (int i = 0; i < 4; i++) a[i] = As[kk][tr + i];
#pragma unroll
            for (int j = 0; j < 4; j++) b[j] = Bs[kk][tc + j];
#pragma unroll
            for (int i = 0; i < 4; i++)
#pragma unroll
                for (int j = 0; j < 4; j++) acc[i][j] = fmaf(a[i], b[j], acc[i][j]);
        }
        __syncthreads();
    }
#pragma unroll
    for (int i = 0; i < 4; i++) {
        int gr = row0 + tr + i;
        if (gr >= n) continue;
#pragma unroll
        for (int j = 0; j < 4; j++) {
            int gc = col0 + tc + j;
            float v = acc[i][j] + bias[gc];
            if (relu) v = fmaxf(v, 0.f);
            C[(size_t)gr * Hh + gc] = v;
        }
    }
}

// ---------------- edge kernels (GATv2 attention) ----------------
// e[m] = dot(leaky_relu(xl[src] + xr[dst]), att); fused segment-max over dst.
__global__ void edge_e_kernel(const void* __restrict__ ei,
                              const float* __restrict__ xl, const float* __restrict__ xr,
                              const float* __restrict__ att,
                              float* __restrict__ e, float* __restrict__ nmax) {
    int w = (blockIdx.x * blockDim.x + threadIdx.x) >> 5;
    int lane = threadIdx.x & 31;
    if (w >= Mm) return;
    int is64 = g_idx64;
    int s, d;
    if (w < Ee) { s = load_idx(ei, w, is64); d = load_idx(ei, (long long)Ee + w, is64); }
    else        { s = d = w - Ee; }
    const float* pl = xl + (size_t)s * Hh;
    const float* pr = xr + (size_t)d * Hh;
    float sum = 0.f;
#pragma unroll
    for (int h = lane; h < Hh; h += 32) {
        float v = pl[h] + pr[h];
        v = (v > 0.f) ? v : 0.2f * v;
        sum = fmaf(v, att[h], sum);
    }
#pragma unroll
    for (int o = 16; o; o >>= 1) sum += __shfl_xor_sync(0xffffffffu, sum, o);
    if (lane == 0) {
        e[w] = sum;
        atomicMaxF(&nmax[d], sum);
    }
}

__global__ void edge_expsum_kernel(const void* __restrict__ ei, float* __restrict__ e,
                                   const float* __restrict__ nmax, float* __restrict__ nsum) {
    int m = blockIdx.x * blockDim.x + threadIdx.x;
    if (m >= Mm) return;
    int is64 = g_idx64;
    int d = (m < Ee) ? load_idx(ei, (long long)Ee + m, is64) : (m - Ee);
    float a = __expf(e[m] - nmax[d]);
    e[m] = a;
    atomicAdd(&nsum[d], a);
}

__global__ void edge_scatter_kernel(const void* __restrict__ ei, const float* __restrict__ e,
                                    const float* __restrict__ nsum, const float* __restrict__ xl,
                                    float* __restrict__ out) {
    int w = (blockIdx.x * blockDim.x + threadIdx.x) >> 5;
    int lane = threadIdx.x & 31;
    if (w >= Mm) return;
    int is64 = g_idx64;
    int s, d;
    if (w < Ee) { s = load_idx(ei, w, is64); d = load_idx(ei, (long long)Ee + w, is64); }
    else        { s = d = w - Ee; }
    float wgt = e[w] / nsum[d];
    const float* pl = xl + (size_t)s * Hh;
    float* po = out + (size_t)d * Hh;
#pragma unroll
    for (int h = lane; h < Hh; h += 32) atomicAdd(&po[h], wgt * pl[h]);
}

// ---------------- layernorm + relu + residual (block per node) ----------------
__global__ void ln_kernel(const float* __restrict__ outbuf, const float* __restrict__ bias_c,
                          const float* __restrict__ lg, const float* __restrict__ lb,
                          float* __restrict__ x) {
    int i = blockIdx.x, t = threadIdx.x;
    __shared__ float red[8];
    float v = outbuf[(size_t)i * Hh + t] + bias_c[t];
    float s = v;
#pragma unroll
    for (int o = 16; o; o >>= 1) s += __shfl_xor_sync(0xffffffffu, s, o);
    if ((t & 31) == 0) red[t >> 5] = s;
    __syncthreads();
    float tot = 0.f;
#pragma unroll
    for (int k = 0; k < 8; k++) tot += red[k];
    float mu = tot * (1.f / Hh);
    float dd = v - mu;
    __syncthreads();
    s = dd * dd;
#pragma unroll
    for (int o = 16; o; o >>= 1) s += __shfl_xor_sync(0xffffffffu, s, o);
    if ((t & 31) == 0) red[t >> 5] = s;
    __syncthreads();
    tot = 0.f;
#pragma unroll
    for (int k = 0; k < 8; k++) tot += red[k];
    float var = tot * (1.f / Hh);
    float y = dd * rsqrtf(var + 1e-5f) * lg[t] + lb[t];
    size_t idx = (size_t)i * Hh + t;
    x[idx] = fmaxf(y, 0.f) + x[idx];
}

// ---------------- gate / pooling ----------------
__global__ void gate_kernel(const float* __restrict__ hid, const float* __restrict__ Wg2,
                            const float* __restrict__ bg2, const void* __restrict__ batch,
                            float* __restrict__ gate, float* __restrict__ bmax) {
    int w = (blockIdx.x * blockDim.x + threadIdx.x) >> 5;
    int lane = threadIdx.x & 31;
    if (w >= Nn) return;
    const float* p = hid + (size_t)w * Hh;
    float sum = 0.f;
#pragma unroll
    for (int h = lane; h < Hh; h += 32) sum = fmaf(p[h], Wg2[h], sum);
#pragma unroll
    for (int o = 16; o; o >>= 1) sum += __shfl_xor_sync(0xffffffffu, sum, o);
    if (lane == 0) {
        float v = sum + bg2[0];
        gate[w] = v;
        atomicMaxF(&bmax[load_idx(batch, w, g_idx64)], v);
    }
}

__global__ void gate_expsum_kernel(float* __restrict__ gate, const float* __restrict__ bmax,
                                   float* __restrict__ bsum, const void* __restrict__ batch) {
    int i = blockIdx.x * blockDim.x + threadIdx.x;
    if (i >= Nn) return;
    int b = load_idx(batch, i, g_idx64);
    float a = __expf(gate[i] - bmax[b]);
    gate[i] = a;
    atomicAdd(&bsum[b], a);
}

__global__ void pool_kernel(const float* __restrict__ gate, const float* __restrict__ bsum,
                            const void* __restrict__ batch, const float* __restrict__ x,
                            float* __restrict__ pooled) {
    int w = (blockIdx.x * blockDim.x + threadIdx.x) >> 5;
    int lane = threadIdx.x & 31;
    if (w >= Nn) return;
    int b = load_idx(batch, w, g_idx64);
    float wg = gate[w] / bsum[b];
    const float* px = x + (size_t)w * Hh;
    float* pp = pooled + (size_t)b * Hh;
#pragma unroll
    for (int h = lane; h < Hh; h += 32) atomicAdd(&pp[h], wg * px[h]);
}

// ---------------- head: z=relu(pooled@Ws^T+bs); cls=z@Wc^T+bc; res=tanh(relu(z@Wr1^T+br1)@Wr2^T+br2)
__global__ void head_kernel(const float* __restrict__ pooled,
                            const float* __restrict__ Ws, const float* __restrict__ bs,
                            const float* __restrict__ Wc, const float* __restrict__ bc,
                            const float* __restrict__ Wr1, const float* __restrict__ br1,
                            const float* __restrict__ Wr2, const float* __restrict__ br2,
                            float* __restrict__ out) {
    int g = blockIdx.x, t = threadIdx.x;
    __shared__ float sp[Hh];
    __shared__ float sz[Hh];
    __shared__ float sr[128];
    sp[t] = pooled[(size_t)g * Hh + t];
    __syncthreads();
    float acc = bs[t];
#pragma unroll 8
    for (int k = 0; k < Hh; k++) acc = fmaf(sp[k], Ws[(size_t)t * Hh + k], acc);
    sz[t] = fmaxf(acc, 0.f);
    __syncthreads();
    if (t < NBc) {
        float a2 = bc[t];
#pragma unroll 8
        for (int k = 0; k < Hh; k++) a2 = fmaf(sz[k], Wc[(size_t)t * Hh + k], a2);
        out[(size_t)g * NBc + t] = a2;
    }
    if (t < 128) {
        float a3 = br1[t];
#pragma unroll 8
        for (int k = 0; k < Hh; k++) a3 = fmaf(sz[k], Wr1[(size_t)t * Hh + k], a3);
        sr[t] = fmaxf(a3, 0.f);
    }
    __syncthreads();
    if (t < 128) {
        float v = sr[t] * Wr2[t];
#pragma unroll
        for (int o = 16; o; o >>= 1) v += __shfl_xor_sync(0xffffffffu, v, o);
        if ((t & 31) == 0) sp[t >> 5] = v;
    }
    __syncthreads();
    if (t == 0) {
        float tot = sp[0] + sp[1] + sp[2] + sp[3] + br2[0];
        out[(size_t)Gg * NBc + g] = tanhf(tot);
    }
}

// ---------------- launch ----------------
extern "C" void kernel_launch(void* const* d_in, const int* in_sizes, int n_in,
                              void* d_out, int out_size) {
    const float* x_in   = (const float*)d_in[0];
    const void*  ei     = d_in[1];
    const void*  batch  = d_in[2];
    const float* W_in   = (const float*)d_in[3];
    const float* b_in   = (const float*)d_in[4];
    const float* Wl     = (const float*)d_in[5];
    const float* bl     = (const float*)d_in[6];
    const float* Wr     = (const float*)d_in[7];
    const float* br     = (const float*)d_in[8];
    const float* att    = (const float*)d_in[9];
    const float* bias_c = (const float*)d_in[10];
    const float* ln_g   = (const float*)d_in[11];
    const float* ln_b   = (const float*)d_in[12];
    const float* Wg1    = (const float*)d_in[13];
    const float* bg1    = (const float*)d_in[14];
    const float* Wg2    = (const float*)d_in[15];
    const float* bg2    = (const float*)d_in[16];
    const float* Ws     = (const float*)d_in[17];
    const float* bs     = (const float*)d_in[18];
    const float* Wc     = (const float*)d_in[19];
    const float* bc     = (const float*)d_in[20];
    const float* Wr1    = (const float*)d_in[21];
    const float* br1    = (const float*)d_in[22];
    const float* Wr2    = (const float*)d_in[23];
    const float* br2    = (const float*)d_in[24];
    float* out = (float*)d_out;

    float *px, *pxl, *pxr, *pout, *pe, *pnmax, *pnsum, *pgate, *pbmax, *pbsum, *ppooled;
    cudaGetSymbolAddress((void**)&px,      g_x);
    cudaGetSymbolAddress((void**)&pxl,     g_xl);
    cudaGetSymbolAddress((void**)&pxr,     g_xr);
    cudaGetSymbolAddress((void**)&pout,    g_out);
    cudaGetSymbolAddress((void**)&pe,      g_e);
    cudaGetSymbolAddress((void**)&pnmax,   g_nmax);
    cudaGetSymbolAddress((void**)&pnsum,   g_nsum);
    cudaGetSymbolAddress((void**)&pgate,   g_gate);
    cudaGetSymbolAddress((void**)&pbmax,   g_bmax);
    cudaGetSymbolAddress((void**)&pbsum,   g_bsum);
    cudaGetSymbolAddress((void**)&ppooled, g_pooled);

    const dim3 gemm_grid(Hh / 64, (Nn + 63) / 64);
    const int EDGE_BLOCKS = (Mm * 32 + 255) / 256;
    const int NODE_W_BLOCKS = (Nn * 32 + 255) / 256;

    detect_kernel<<<1, 1>>>(ei);

    // input projection: x = x_in @ W_in^T + b_in
    sgemm_tn_kernel<<<gemm_grid, 256>>>(x_in, W_in, b_in, px, Nn, IND, 0);

    for (int l = 0; l < Ll; l++) {
        sgemm_tn_kernel<<<gemm_grid, 256>>>(px, Wl + (size_t)l * Hh * Hh, bl + l * Hh, pxl, Nn, Hh, 0);
        sgemm_tn_kernel<<<gemm_grid, 256>>>(px, Wr + (size_t)l * Hh * Hh, br + l * Hh, pxr, Nn, Hh, 0);
        fill_kernel<<<(Nn + 255) / 256, 256>>>(pnmax, -INFINITY, Nn);
        fill_kernel<<<(Nn + 255) / 256, 256>>>(pnsum, 0.f, Nn);
        fill_kernel<<<(Nn * Hh + 255) / 256, 256>>>(pout, 0.f, Nn * Hh);
        edge_e_kernel<<<EDGE_BLOCKS, 256>>>(ei, pxl, pxr, att + l * Hh, pe, pnmax);
        edge_expsum_kernel<<<(Mm + 255) / 256, 256>>>(ei, pe, pnmax, pnsum);
        edge_scatter_kernel<<<EDGE_BLOCKS, 256>>>(ei, pe, pnsum, pxl, pout);
        ln_kernel<<<Nn, Hh>>>(pout, bias_c + l * Hh, ln_g + l * Hh, ln_b + l * Hh, px);
    }

    // gate MLP hidden (reuse g_xl)
    sgemm_tn_kernel<<<gemm_grid, 256>>>(px, Wg1, bg1, pxl, Nn, Hh, 1);
    fill_kernel<<<1, 64>>>(pbmax, -INFINITY, Gg);
    fill_kernel<<<1, 64>>>(pbsum, 0.f, Gg);
    fill_kernel<<<(Gg * Hh + 255) / 256, 256>>>(ppooled, 0.f, Gg * Hh);
    gate_kernel<<<NODE_W_BLOCKS, 256>>>(pxl, Wg2, bg2, batch, pgate, pbmax);
    gate_expsum_kernel<<<(Nn + 255) / 256, 256>>>(pgate, pbmax, pbsum, batch);
    pool_kernel<<<NODE_W_BLOCKS, 256>>>(pgate, pbsum, batch, px, ppooled);
    head_kernel<<<Gg, Hh>>>(ppooled, Ws, bs, Wc, bc, Wr1, br1, Wr2, br2, out);
}